// round 9
// baseline (speedup 1.0000x reference)
#include <cuda_runtime.h>
#include <cuda_bf16.h>

// StateSpaceLayer: out[b,t,r,c] = sum_{j<=t} A[r]^(t-j) * x[b,j,r,c]
// == per-(b,r,c) linear recurrence y_t = A[r]*y_{t-1} + x_t.
// x, out: (B,SEQ,D,D) fp32; A: (D,) fp32.  B=4, SEQ=512, D=64.
//
// R9: decompose along the CONTIGUOUS (r,c) slab axis. Thread = one float4
// lane (4 consecutive c of one r -> one shared decay a); warp = 512B fully
// contiguous; each lane is an independent serial scan -> no smem combine at
// all. Sequence is split into 32 chunks of 16 timesteps across blocks with
// single-pass decoupled lookback through L2 (per-lane aggregate + inclusive,
// Horner fold => bit-identical result regardless of lookback depth).
// Cross-replay flag reuse handled by monotonic epochs derived from each
// block's own previous flag value (no reset kernel needed).

#define SEQ    512
#define D      64
#define L      16              // timesteps per chunk
#define NTC    (SEQ/L)         // 32 chunks
#define SLAB4  ((D*D)/4)       // 1024 float4 per timestep
#define TPB    512             // threads = f4 lanes per half-slab
#define MAXBLK 512

__device__ float4   g_agg[MAXBLK * TPB];   // per-lane local aggregate
__device__ float4   g_inc[MAXBLK * TPB];   // per-lane inclusive prefix
__device__ unsigned g_stat[MAXBLK];        // 2*epoch = agg ready, +1 = inc ready

static __device__ __forceinline__ unsigned ld_acq(const unsigned* p) {
    unsigned v;
    asm volatile("ld.acquire.gpu.u32 %0, [%1];" : "=r"(v) : "l"(p) : "memory");
    return v;
}
static __device__ __forceinline__ void st_rel(unsigned* p, unsigned v) {
    asm volatile("st.release.gpu.u32 [%0], %1;" :: "l"(p), "r"(v) : "memory");
}

__global__ __launch_bounds__(TPB, 1)
void ssm_scan_kernel(const float4* __restrict__ x,
                     const float* __restrict__ A,
                     float4* __restrict__ out,
                     int Bsub)                       // Bsub = B*2
{
    const int bid = blockIdx.x;
    const int tc  = bid / Bsub;                      // time-chunk (low bids = early)
    const int sub = bid - tc * Bsub;                 // (b, half)
    const int b   = sub >> 1;
    const int tid = threadIdx.x;

    const int lam = (sub & 1) * TPB + tid;           // f4 lane in slab [0,1024)
    const int r   = lam >> 4;                        // 16 f4 lanes per r

    const float a = fmaxf(__ldg(A + r), 1e-6f);      // reference clips at EPS
    const float a2 = a * a, a4 = a2 * a2, a8 = a4 * a4;
    const float aL = a8 * a8;                        // a^16

    const size_t base = (size_t)(b * SEQ + tc * L) * SLAB4 + lam;
    const float4* __restrict__ xp = x + base;

    // ---- load 16 t (LDG.128, warp = 512B contiguous) + local scan ----
    float4 v[L];
    #pragma unroll
    for (int i = 0; i < L; i++)
        v[i] = xp[(size_t)i * SLAB4];
    #pragma unroll
    for (int i = 1; i < L; i++) {
        v[i].x = fmaf(a, v[i-1].x, v[i].x);
        v[i].y = fmaf(a, v[i-1].y, v[i].y);
        v[i].z = fmaf(a, v[i-1].z, v[i].z);
        v[i].w = fmaf(a, v[i-1].w, v[i].w);
    }

    __shared__ unsigned s_epoch;
    __shared__ int      s_stop;
    if (tid == 0) s_epoch = g_stat[bid] / 2 + 1;     // monotonic per-replay epoch

    // ---- publish per-lane aggregate ----
    g_agg[bid * TPB + tid] = v[L-1];
    __threadfence();
    __syncthreads();
    const unsigned epoch = s_epoch;
    if (tid == 0) st_rel(&g_stat[bid], 2 * epoch);

    // ---- lookback: tid0 finds stop point (inclusive) / depth ----
    if (tid == 0) {
        int stop = -1;
        for (int p = tc - 1; p >= 0; p--) {
            const unsigned* st = &g_stat[p * Bsub + sub];
            unsigned sv;
            while ((sv = ld_acq(st)) < 2 * epoch) __nanosleep(32);
            if (sv == 2 * epoch + 1) { stop = p; break; }   // inclusive ready
        }
        s_stop = stop;
    }
    __syncthreads();
    const int stop = s_stop;

    // ---- fold carry (Horner, ascending: value independent of stop depth) ----
    float4 E = make_float4(0.f, 0.f, 0.f, 0.f);
    if (stop >= 0) E = g_inc[(stop * Bsub + sub) * TPB + tid];
    for (int p = stop + 1; p < tc; p++) {
        float4 ag = g_agg[(p * Bsub + sub) * TPB + tid];
        E.x = fmaf(aL, E.x, ag.x);
        E.y = fmaf(aL, E.y, ag.y);
        E.z = fmaf(aL, E.z, ag.z);
        E.w = fmaf(aL, E.w, ag.w);
    }

    // ---- publish inclusive prefix (unblocks successors early) ----
    float4 inc;
    inc.x = fmaf(aL, E.x, v[L-1].x);
    inc.y = fmaf(aL, E.y, v[L-1].y);
    inc.z = fmaf(aL, E.z, v[L-1].z);
    inc.w = fmaf(aL, E.w, v[L-1].w);
    g_inc[bid * TPB + tid] = inc;
    __threadfence();
    __syncthreads();
    if (tid == 0) st_rel(&g_stat[bid], 2 * epoch + 1);

    // ---- apply carry + store (STG.128, warp = 512B contiguous) ----
    float4* __restrict__ op = out + base;
    float pw = a;
    #pragma unroll
    for (int i = 0; i < L; i++) {
        float4 o;
        o.x = fmaf(pw, E.x, v[i].x);
        o.y = fmaf(pw, E.y, v[i].y);
        o.z = fmaf(pw, E.z, v[i].z);
        o.w = fmaf(pw, E.w, v[i].w);
        op[(size_t)i * SLAB4] = o;
        pw *= a;
    }
}

extern "C" void kernel_launch(void* const* d_in, const int* in_sizes, int n_in,
                              void* d_out, int out_size)
{
    // Identify x vs A by element count (A has D=64 elements).
    const float* x = (const float*)d_in[0];
    const float* A = (const float*)d_in[1];
    long nx = in_sizes[0];
    if (n_in >= 2 && in_sizes[0] == D && in_sizes[1] > D) {
        x = (const float*)d_in[1];
        A = (const float*)d_in[0];
        nx = in_sizes[1];
    }
    const int B    = (int)(nx / ((long)SEQ * D * D));   // 4
    const int Bsub = B * 2;

    dim3 grid(NTC * Bsub);    // 256 blocks; low bid = early time chunk
    dim3 block(TPB);
    ssm_scan_kernel<<<grid, block>>>((const float4*)x, A, (float4*)d_out, Bsub);
}

// round 10
// speedup vs baseline: 1.6645x; 1.6645x over previous
#include <cuda_runtime.h>
#include <cuda_bf16.h>

// StateSpaceLayer: out[b,t,r,c] = sum_{j<=t} A[r]^(t-j) * x[b,j,r,c]
// == per-(b,r,c) linear recurrence y_t = A[r]*y_{t-1} + x_t.
// x, out: (B,SEQ,D,D) fp32; A: (D,) fp32.  B=4, SEQ=512, D=64.
//
// R10: R8's winning block structure (block = (b,r), 512 thr, occ 2, grid 256
// single wave, prefetch-past-barrier, thread-parallel Horner combine,
// double-buffered smem) with FLOAT4 payload: 16 f4 lanes cover the 64-c row,
// 32 chunks x 4 timesteps per pass, 4 passes. Halves R8's LSU issue cost
// (LDG.128/STG.128) while keeping v[2][4] float4 = 32 data regs -> occ 2.

#define SEQ    512
#define D      64
#define LCH    4              // timesteps per chunk per pass
#define NC     32             // chunks per pass
#define PASS_T (NC*LCH)       // 128 timesteps per pass
#define NPASS  4
#define TPB    512            // 32 chunks x 16 f4 lanes
#define TS4    ((D*D)/4)      // timestep stride in float4 = 1024

__global__ __launch_bounds__(TPB, 2)
void ssm_scan_kernel(const float4* __restrict__ x,
                     const float* __restrict__ A,
                     float4* __restrict__ out)
{
    // grid = B * D : block covers (b, r) and the full 64-c row
    const int bid = blockIdx.x;
    const int r   = bid & (D - 1);
    const int b   = bid >> 6;

    const int tid = threadIdx.x;
    const int l   = tid & 15;            // f4 lane within row: c = 4l..4l+3
    const int k   = tid >> 4;            // chunk index 0..NC-1

    const float a  = fmaxf(A[r], 1e-6f); // reference clips at EPS=1e-6
    const float a2 = a * a;
    const float aL = a2 * a2;            // per-chunk decay a^4

    // float4 index for (b, t, r, 4l): (b*SEQ + t)*TS4 + r*16 + l
    const long rowoff = (long)r * 16 + l;
    const float4* __restrict__ xb = x + (long)b * SEQ * TS4 + rowoff;
    float4* __restrict__ ob       = out + (long)b * SEQ * TS4 + rowoff;

    __shared__ float4 s_end[2][NC][17];  // chunk-end partials (padded rows)
    __shared__ float4 s_tot[2][16];      // running carry across passes

    if (tid < 16) s_tot[1][tid] = make_float4(0.f, 0.f, 0.f, 0.f);

    // ---- prologue: load pass 0 ----
    float4 v[2][LCH];
    {
        const float4* __restrict__ xp = xb + (long)(k * LCH) * TS4;
        #pragma unroll
        for (int i = 0; i < LCH; i++)
            v[0][i] = xp[(long)i * TS4];
    }

    #pragma unroll
    for (int p = 0; p < NPASS; p++) {
        const int cur = p & 1;
        const int nxt = cur ^ 1;

        // ---- prefetch next pass BEFORE this pass's barrier ----
        if (p + 1 < NPASS) {
            const float4* __restrict__ xp =
                xb + (long)((p + 1) * PASS_T + k * LCH) * TS4;
            #pragma unroll
            for (int i = 0; i < LCH; i++)
                v[nxt][i] = xp[(long)i * TS4];
        }

        // ---- local inclusive scan of current pass ----
        #pragma unroll
        for (int i = 1; i < LCH; i++) {
            v[cur][i].x = fmaf(a, v[cur][i-1].x, v[cur][i].x);
            v[cur][i].y = fmaf(a, v[cur][i-1].y, v[cur][i].y);
            v[cur][i].z = fmaf(a, v[cur][i-1].z, v[cur][i].z);
            v[cur][i].w = fmaf(a, v[cur][i-1].w, v[cur][i].w);
        }
        s_end[cur][k][l] = v[cur][LCH - 1];

        __syncthreads();  // s_end[cur] + s_tot[(p+1)&1] visible; nxt loads in flight

        // ---- thread-parallel combine: exclusive carry into chunk k ----
        float4 E = s_tot[(p + 1) & 1][l];        // seed = prev pass total
        for (int m = 0; m < k; m++) {
            float4 e = s_end[cur][m][l];
            E.x = fmaf(aL, E.x, e.x);
            E.y = fmaf(aL, E.y, e.y);
            E.z = fmaf(aL, E.z, e.z);
            E.w = fmaf(aL, E.w, e.w);
        }
        if (k == NC - 1) {
            float4 e = s_end[cur][NC - 1][l];
            float4 T;
            T.x = fmaf(aL, E.x, e.x);
            T.y = fmaf(aL, E.y, e.y);
            T.z = fmaf(aL, E.z, e.z);
            T.w = fmaf(aL, E.w, e.w);
            s_tot[p & 1][l] = T;                 // consumed after NEXT barrier
        }

        // ---- apply carry and store: out_i = v_i + a^(i+1) * E ----
        float4* __restrict__ op = ob + (long)(p * PASS_T + k * LCH) * TS4;
        float pw = a;
        #pragma unroll
        for (int i = 0; i < LCH; i++) {
            float4 o;
            o.x = fmaf(pw, E.x, v[cur][i].x);
            o.y = fmaf(pw, E.y, v[cur][i].y);
            o.z = fmaf(pw, E.z, v[cur][i].z);
            o.w = fmaf(pw, E.w, v[cur][i].w);
            op[(long)i * TS4] = o;
            pw *= a;
        }
    }
}

extern "C" void kernel_launch(void* const* d_in, const int* in_sizes, int n_in,
                              void* d_out, int out_size)
{
    // Identify x vs A by element count (A has D=64 elements).
    const float* x = (const float*)d_in[0];
    const float* A = (const float*)d_in[1];
    long nx = in_sizes[0];
    if (n_in >= 2 && in_sizes[0] == D && in_sizes[1] > D) {
        x = (const float*)d_in[1];
        A = (const float*)d_in[0];
        nx = in_sizes[1];
    }
    const int B = (int)(nx / ((long)SEQ * D * D));   // 4

    dim3 grid(B * D);
    dim3 block(TPB);
    ssm_scan_kernel<<<grid, block>>>((const float4*)x, A, (float4*)d_out);
}

// round 11
// speedup vs baseline: 1.9075x; 1.1460x over previous
#include <cuda_runtime.h>
#include <cuda_bf16.h>

// StateSpaceLayer: out[b,t,r,c] = sum_{j<=t} A[r]^(t-j) * x[b,j,r,c]
// == per-(b,r,c) linear recurrence y_t = A[r]*y_{t-1} + x_t.
// x, out: (B,SEQ,D,D) fp32; A: (D,) fp32.  B=4, SEQ=512, D=64.
//
// R11: float4 payload + LOG-DEPTH combine. Block = (b,r) (a is uniform per
// block), 512 thr, grid 256 (one resident wave at occ 2). 32 chunks x 4
// timesteps per pass, 4 passes, next-pass loads prefetched past the barrier.
// Cross-chunk carries via per-warp Kogge-Stone shuffle scan (scalar step
// multipliers a^4, a^8, a^16, ... since a is uniform): warp w scans the 32
// chunk-ends of f4-lane w, seeded with the cross-pass carry C held in
// registers. Per-thread smem drops from ~16 LDS.128/pass (R10) to 2 LDS+2 STS.

#define SEQ    512
#define D      64
#define LCH    4              // timesteps per chunk per pass
#define NC     32             // chunks per pass
#define PASS_T (NC*LCH)       // 128 timesteps per pass
#define NPASS  4
#define TPB    512            // 32 chunks x 16 f4 lanes
#define TS4    ((D*D)/4)      // timestep stride in float4 = 1024

__global__ __launch_bounds__(TPB, 2)
void ssm_scan_kernel(const float4* __restrict__ x,
                     const float* __restrict__ A,
                     float4* __restrict__ out)
{
    // grid = B * D : block covers (b, r) and the full 64-c row
    const int bid = blockIdx.x;
    const int r   = bid & (D - 1);
    const int b   = bid >> 6;

    const int tid  = threadIdx.x;
    const int l    = tid & 15;           // f4 lane within row: c = 4l..4l+3
    const int k    = tid >> 4;           // chunk index 0..NC-1
    const int wid  = tid >> 5;           // warp id 0..15  (scans f4-lane wid)
    const int lane = tid & 31;           // lane in warp = chunk index in scan

    const float a  = fmaxf(A[r], 1e-6f); // reference clips at EPS=1e-6
    const float a2 = a * a;
    const float aL = a2 * a2;            // per-chunk decay a^4

    const long rowoff = (long)r * 16;
    const float4* __restrict__ xb = x   + (long)b * SEQ * TS4 + rowoff + l;
    float4* __restrict__ ob       = out + (long)b * SEQ * TS4 + rowoff + l;

    __shared__ float4 s_end[NC][17];     // chunk-end partials (padded rows)
    __shared__ float4 s_pre[NC][17];     // exclusive carries   (padded rows)

    float4 C = make_float4(0.f, 0.f, 0.f, 0.f);   // per-warp cross-pass carry

    // ---- prologue: load pass 0 ----
    float4 v[2][LCH];
    {
        const float4* __restrict__ xp = xb + (long)(k * LCH) * TS4;
        #pragma unroll
        for (int i = 0; i < LCH; i++)
            v[0][i] = xp[(long)i * TS4];
    }

    #pragma unroll
    for (int p = 0; p < NPASS; p++) {
        const int cur = p & 1;
        const int nxt = cur ^ 1;

        // ---- prefetch next pass BEFORE this pass's barriers ----
        if (p + 1 < NPASS) {
            const float4* __restrict__ xp =
                xb + (long)((p + 1) * PASS_T + k * LCH) * TS4;
            #pragma unroll
            for (int i = 0; i < LCH; i++)
                v[nxt][i] = xp[(long)i * TS4];
        }

        // ---- local inclusive scan of current chunk ----
        #pragma unroll
        for (int i = 1; i < LCH; i++) {
            v[cur][i].x = fmaf(a, v[cur][i-1].x, v[cur][i].x);
            v[cur][i].y = fmaf(a, v[cur][i-1].y, v[cur][i].y);
            v[cur][i].z = fmaf(a, v[cur][i-1].z, v[cur][i].z);
            v[cur][i].w = fmaf(a, v[cur][i-1].w, v[cur][i].w);
        }
        s_end[k][l] = v[cur][LCH - 1];   // warp writes 512B contiguous

        __syncthreads();                 // barrier 1: s_end visible

        // ---- per-warp Kogge-Stone over chunk axis (lane = chunk) ----
        // sequence scanned: [C, s_0, ..., s_30]; inclusive result at lane t
        // equals the EXCLUSIVE carry into chunk t.
        float4 sv = (lane == 0) ? C : s_end[lane - 1][wid];
        float m = aL;
        #pragma unroll
        for (int off = 1; off < 32; off <<= 1) {
            float4 up;
            up.x = __shfl_up_sync(0xffffffffu, sv.x, off);
            up.y = __shfl_up_sync(0xffffffffu, sv.y, off);
            up.z = __shfl_up_sync(0xffffffffu, sv.z, off);
            up.w = __shfl_up_sync(0xffffffffu, sv.w, off);
            if (lane >= off) {
                sv.x = fmaf(m, up.x, sv.x);
                sv.y = fmaf(m, up.y, sv.y);
                sv.z = fmaf(m, up.z, sv.z);
                sv.w = fmaf(m, up.w, sv.w);
            }
            m = m * m;
        }
        s_pre[lane][wid] = sv;           // exclusive carry for (chunk=lane, l=wid)

        // cross-pass carry: C' = s_31 + a^4 * E_excl(31), computed at lane 31
        {
            float4 Cn;
            if (lane == 31) {
                float4 e = s_end[NC - 1][wid];
                Cn.x = fmaf(aL, sv.x, e.x);
                Cn.y = fmaf(aL, sv.y, e.y);
                Cn.z = fmaf(aL, sv.z, e.z);
                Cn.w = fmaf(aL, sv.w, e.w);
            }
            C.x = __shfl_sync(0xffffffffu, Cn.x, 31);
            C.y = __shfl_sync(0xffffffffu, Cn.y, 31);
            C.z = __shfl_sync(0xffffffffu, Cn.z, 31);
            C.w = __shfl_sync(0xffffffffu, Cn.w, 31);
        }

        __syncthreads();                 // barrier 2: s_pre visible

        // ---- apply carry and store: out_i = v_i + a^(i+1) * E ----
        const float4 E = s_pre[k][l];
        float4* __restrict__ op = ob + (long)(p * PASS_T + k * LCH) * TS4;
        float pw = a;
        #pragma unroll
        for (int i = 0; i < LCH; i++) {
            float4 o;
            o.x = fmaf(pw, E.x, v[cur][i].x);
            o.y = fmaf(pw, E.y, v[cur][i].y);
            o.z = fmaf(pw, E.z, v[cur][i].z);
            o.w = fmaf(pw, E.w, v[cur][i].w);
            op[(long)i * TS4] = o;
            pw *= a;
        }
    }
}

extern "C" void kernel_launch(void* const* d_in, const int* in_sizes, int n_in,
                              void* d_out, int out_size)
{
    // Identify x vs A by element count (A has D=64 elements).
    const float* x = (const float*)d_in[0];
    const float* A = (const float*)d_in[1];
    long nx = in_sizes[0];
    if (n_in >= 2 && in_sizes[0] == D && in_sizes[1] > D) {
        x = (const float*)d_in[1];
        A = (const float*)d_in[0];
        nx = in_sizes[1];
    }
    const int B = (int)(nx / ((long)SEQ * D * D));   // 4

    dim3 grid(B * D);
    dim3 block(TPB);
    ssm_scan_kernel<<<grid, block>>>((const float4*)x, A, (float4*)d_out);
}

// round 12
// speedup vs baseline: 1.9600x; 1.0275x over previous
#include <cuda_runtime.h>
#include <cuda_bf16.h>

// StateSpaceLayer: out[b,t,r,c] = sum_{j<=t} A[r]^(t-j) * x[b,j,r,c]
// == per-(b,r,c) linear recurrence y_t = A[r]*y_{t-1} + x_t.
// x, out: (B,SEQ,D,D) fp32; A: (D,) fp32.  B=4, SEQ=512, D=64.
//
// R12 = R8 (best: 10.7us) + ONE change: the cross-chunk Horner combine is
// unrolled to a fixed 15 iterations with (m < k) predication. The 15 LDS.64
// become unconditional independent loads ptxas can batch (overlapped
// latency) instead of a serial LDS->FMA chain of up to 15x33 cyc that the
// tail thread imposed on every pass's barrier. Values are bit-identical.
// Everything else (float2, warp = 32 contiguous lanes of one chunk, occ 2,
// grid 256 single wave, prefetch-past-barrier, double-buffered s_tot) is
// unchanged from R8.

#define SEQ   512
#define D     64
#define LCH   8             // timesteps per chunk per pass (float2 regs)
#define NC    16            // chunks per pass
#define PASS_T (NC*LCH)     // 128 timesteps per pass
#define NPASS 4
#define TPB   (NC*32)       // 512 threads
#define TS2   ((D*D)/2)     // timestep stride in float2 = 2048

__global__ __launch_bounds__(TPB, 2)
void ssm_scan_kernel(const float2* __restrict__ x,
                     const float* __restrict__ A,
                     float2* __restrict__ out)
{
    // grid = B * D : block covers (b, r) and the full c-row
    const int bid = blockIdx.x;
    const int r   = bid & (D - 1);
    const int b   = bid >> 6;

    const int tid = threadIdx.x;
    const int l   = tid & 31;            // float2 lane: c = 2l, 2l+1
    const int k   = tid >> 5;            // chunk index 0..NC-1

    const float a = fmaxf(A[r], 1e-6f);  // reference clips at EPS=1e-6
    const float a2 = a * a;
    const float a4 = a2 * a2;
    const float a8 = a4 * a4;            // per-chunk decay (a^LCH)

    // float2 base for (b, t, r, 2l): index = (b*SEQ + t)*TS2 + r*32 + l
    const long rowoff = (long)r * 32 + l;
    const float2* __restrict__ xb = x + (long)b * SEQ * TS2 + rowoff;
    float2* __restrict__ ob       = out + (long)b * SEQ * TS2 + rowoff;

    __shared__ float2 s_end[2][NC][33];  // chunk-end partials (padded rows)
    __shared__ float2 s_tot[2][32];      // running carry across passes

    if (tid < 32) s_tot[1][tid] = make_float2(0.0f, 0.0f);

    // ---- prologue: load pass 0 ----
    float2 v[2][LCH];
    {
        const float2* __restrict__ xp = xb + (long)(k * LCH) * TS2;
        #pragma unroll
        for (int i = 0; i < LCH; i++)
            v[0][i] = xp[(long)i * TS2];
    }

    #pragma unroll
    for (int p = 0; p < NPASS; p++) {
        const int cur = p & 1;
        const int nxt = cur ^ 1;

        // ---- prefetch next pass BEFORE this pass's barrier ----
        if (p + 1 < NPASS) {
            const float2* __restrict__ xp =
                xb + (long)((p + 1) * PASS_T + k * LCH) * TS2;
            #pragma unroll
            for (int i = 0; i < LCH; i++)
                v[nxt][i] = xp[(long)i * TS2];
        }

        // ---- local inclusive scan of current pass ----
        #pragma unroll
        for (int i = 1; i < LCH; i++) {
            v[cur][i].x = fmaf(a, v[cur][i - 1].x, v[cur][i].x);
            v[cur][i].y = fmaf(a, v[cur][i - 1].y, v[cur][i].y);
        }
        s_end[cur][k][l] = v[cur][LCH - 1];

        __syncthreads();  // s_end[cur] + s_tot[(p+1)&1] visible; nxt loads in flight

        // ---- combine: exclusive carry into chunk k ----
        // Fixed-trip unrolled with (m < k) predication: the NC-1 LDS are
        // unconditional + independent (batchable); the fold is predicated
        // FMAs, bit-identical to the variable-trip Horner.
        float2 E = s_tot[(p + 1) & 1][l];        // seed = prev pass total
        #pragma unroll
        for (int m = 0; m < NC - 1; m++) {
            float2 e = s_end[cur][m][l];
            if (m < k) {
                E.x = fmaf(a8, E.x, e.x);
                E.y = fmaf(a8, E.y, e.y);
            }
        }
        if (k == NC - 1) {
            float2 e = s_end[cur][NC - 1][l];
            float2 T;
            T.x = fmaf(a8, E.x, e.x);
            T.y = fmaf(a8, E.y, e.y);
            s_tot[p & 1][l] = T;                 // consumed after NEXT barrier
        }

        // ---- apply carry and store: out_i = v_i + a^(i+1) * E ----
        float2* __restrict__ op = ob + (long)(p * PASS_T + k * LCH) * TS2;
        float pw = a;
        #pragma unroll
        for (int i = 0; i < LCH; i++) {
            float2 o;
            o.x = fmaf(pw, E.x, v[cur][i].x);
            o.y = fmaf(pw, E.y, v[cur][i].y);
            op[(long)i * TS2] = o;
            pw *= a;
        }
    }
}

extern "C" void kernel_launch(void* const* d_in, const int* in_sizes, int n_in,
                              void* d_out, int out_size)
{
    // Identify x vs A by element count (A has D=64 elements).
    const float* x = (const float*)d_in[0];
    const float* A = (const float*)d_in[1];
    long nx = in_sizes[0];
    if (n_in >= 2 && in_sizes[0] == D && in_sizes[1] > D) {
        x = (const float*)d_in[1];
        A = (const float*)d_in[0];
        nx = in_sizes[1];
    }
    const int B = (int)(nx / ((long)SEQ * D * D));   // 4

    dim3 grid(B * D);
    dim3 block(TPB);
    ssm_scan_kernel<<<grid, block>>>((const float2*)x, A, (float2*)d_out);
}

// round 13
// speedup vs baseline: 2.3403x; 1.1940x over previous
#include <cuda_runtime.h>
#include <cuda_bf16.h>

// StateSpaceLayer: out[b,t,r,c] = sum_{j<=t} A[r]^(t-j) * x[b,j,r,c]
// == per-(b,r,c) linear recurrence y_t = A[r]*y_{t-1} + x_t.
// x, out: (B,SEQ,D,D) fp32; A: (D,) fp32.  B=4, SEQ=512, D=64.
//
// R13: float2 memory path (proven) + SMALL blocks at HIGH occupancy +
// SHALLOW combine. TPB=256 = 8 chunks x 32 f2 lanes (full c-row, block =
// (b,r), grid 256). LCH=16, NPASS=4. Single-buffered v[16] (~52 regs) ->
// 4-5 resident blocks/SM: inter-block stagger replaces R8's register-hungry
// intra-block prefetch. Combine depth is only 7 (NC=8), so the cross-chunk
// fold costs ~7 LDS + 7 FMA instead of 15x33 serial cycles. Barriers span
// just 8 warps. s_end/s_tot double-buffered for cross-barrier WAR safety.

#define SEQ    512
#define D      64
#define LCH    16             // timesteps per chunk per pass
#define NC     8              // chunks per pass
#define PASS_T (NC*LCH)       // 128 timesteps per pass
#define NPASS  4
#define TPB    (NC*32)        // 256 threads
#define TS2    ((D*D)/2)      // timestep stride in float2 = 2048

__global__ __launch_bounds__(TPB, 4)
void ssm_scan_kernel(const float2* __restrict__ x,
                     const float* __restrict__ A,
                     float2* __restrict__ out)
{
    // grid = B * D : block covers (b, r) and the full 64-c row
    const int bid = blockIdx.x;
    const int r   = bid & (D - 1);
    const int b   = bid >> 6;

    const int tid = threadIdx.x;
    const int l   = tid & 31;            // float2 lane: c = 2l, 2l+1
    const int k   = tid >> 5;            // chunk index 0..NC-1

    const float a = fmaxf(A[r], 1e-6f);  // reference clips at EPS=1e-6
    const float a2  = a * a;
    const float a4  = a2 * a2;
    const float a8  = a4 * a4;
    const float aL  = a8 * a8;           // per-chunk decay a^16

    // float2 base for (b, t, r, 2l): index = (b*SEQ + t)*TS2 + r*32 + l
    const long rowoff = (long)r * 32 + l;
    const float2* __restrict__ xb = x   + (long)b * SEQ * TS2 + rowoff;
    float2* __restrict__ ob       = out + (long)b * SEQ * TS2 + rowoff;

    __shared__ float2 s_end[2][NC][33];  // chunk-end partials (padded rows)
    __shared__ float2 s_tot[2][32];      // running carry across passes

    if (tid < 32) s_tot[1][tid] = make_float2(0.0f, 0.0f);

    #pragma unroll
    for (int p = 0; p < NPASS; p++) {
        const int cur = p & 1;

        // ---- load chunk: 16 independent LDG.64, warp = 256B contiguous ----
        const float2* __restrict__ xp = xb + (long)(p * PASS_T + k * LCH) * TS2;
        float2 v[LCH];
        #pragma unroll
        for (int i = 0; i < LCH; i++)
            v[i] = xp[(long)i * TS2];

        // ---- local inclusive scan ----
        #pragma unroll
        for (int i = 1; i < LCH; i++) {
            v[i].x = fmaf(a, v[i - 1].x, v[i].x);
            v[i].y = fmaf(a, v[i - 1].y, v[i].y);
        }
        s_end[cur][k][l] = v[LCH - 1];

        __syncthreads();   // s_end[cur] + s_tot[(p+1)&1] visible

        // ---- shallow combine: exclusive carry into chunk k (depth <= 7) ----
        float2 E = s_tot[(p + 1) & 1][l];        // seed = prev pass total
        #pragma unroll
        for (int m = 0; m < NC - 1; m++) {
            float2 e = s_end[cur][m][l];
            if (m < k) {
                E.x = fmaf(aL, E.x, e.x);
                E.y = fmaf(aL, E.y, e.y);
            }
        }
        if (k == NC - 1) {
            float2 e = s_end[cur][NC - 1][l];
            float2 T;
            T.x = fmaf(aL, E.x, e.x);
            T.y = fmaf(aL, E.y, e.y);
            s_tot[p & 1][l] = T;                 // consumed after NEXT barrier
        }

        // ---- apply carry and store: out_i = v_i + a^(i+1) * E ----
        float2* __restrict__ op = ob + (long)(p * PASS_T + k * LCH) * TS2;
        float pw = a;
        #pragma unroll
        for (int i = 0; i < LCH; i++) {
            float2 o;
            o.x = fmaf(pw, E.x, v[i].x);
            o.y = fmaf(pw, E.y, v[i].y);
            op[(long)i * TS2] = o;
            pw *= a;
        }
    }
}

extern "C" void kernel_launch(void* const* d_in, const int* in_sizes, int n_in,
                              void* d_out, int out_size)
{
    // Identify x vs A by element count (A has D=64 elements).
    const float* x = (const float*)d_in[0];
    const float* A = (const float*)d_in[1];
    long nx = in_sizes[0];
    if (n_in >= 2 && in_sizes[0] == D && in_sizes[1] > D) {
        x = (const float*)d_in[1];
        A = (const float*)d_in[0];
        nx = in_sizes[1];
    }
    const int B = (int)(nx / ((long)SEQ * D * D));   // 4

    dim3 grid(B * D);
    dim3 block(TPB);
    ssm_scan_kernel<<<grid, block>>>((const float2*)x, A, (float2*)d_out);
}